// round 4
// baseline (speedup 1.0000x reference)
#include <cuda_runtime.h>
#include <cuda_fp16.h>
#include <cstdint>

#define B_  4
#define C_  512
#define CI_ 256
#define N_  4096
#define EPS_ 1e-5f
#define RSCALE 64.0f

// ------------------------- device scratch (no allocs) -------------------------
// all operands pre-split into fp16 hi/lo pairs
__device__ half vT_hi[B_ * N_ * C_],  vT_lo[B_ * N_ * C_];      // [B,N,C]
__device__ half Wg_hi[CI_ * C_],      Wg_lo[CI_ * C_];
__device__ half Wth_hi[CI_ * C_],     Wth_lo[CI_ * C_];
__device__ half Wph_hi[CI_ * C_],     Wph_lo[CI_ * C_];
__device__ half Ww_hi[C_ * CI_],      Ww_lo[C_ * CI_];
__device__ half th_hi[B_ * N_ * CI_], th_lo[B_ * N_ * CI_];     // [B,N,Ci]
__device__ half ph_hi[B_ * N_ * CI_], ph_lo[B_ * N_ * CI_];     // [B,N,Ci]
__device__ half g_hi [B_ * CI_ * N_], g_lo [B_ * CI_ * N_];     // [B,Ci,N]
__device__ half y_hi [B_ * N_ * CI_], y_lo [B_ * N_ * CI_];     // [B,N,Ci]
__device__ half R_hi [(long)B_ * N_ * N_];                       // 128 MB
__device__ half R_lo [(long)B_ * N_ * N_];                       // 128 MB
__device__ float Wy_buf[B_ * C_ * N_];                           // 32 MB
__device__ float bn_mean[C_];
__device__ float bn_rstd[C_];

// ------------------------------- GEMM config ----------------------------------
// tile 128(M) x 128(N) x 32(K-halves); smem rows pitched to 80B (conflict-free
// for both cp.async stores and ldmatrix phases: word offs 20r mod 32 distinct).
#define PITCH_B 80
#define TILE_B  (128 * PITCH_B)          // 10240 B per tile matrix
#define SMEM_GEMM_BYTES (8 * TILE_B)     // {Ah,Al,Bh,Bl} x 2 buffers = 81920

__device__ __forceinline__ uint32_t smem_u32(const void* p) {
    uint32_t a;
    asm("{ .reg .u64 t; cvta.to.shared.u64 t, %1; cvt.u32.u64 %0, t; }" : "=r"(a) : "l"(p));
    return a;
}
__device__ __forceinline__ void cp_async16(uint32_t saddr, const void* gaddr) {
    asm volatile("cp.async.cg.shared.global [%0], [%1], 16;" :: "r"(saddr), "l"(gaddr));
}
#define CP_COMMIT() asm volatile("cp.async.commit_group;" ::: "memory")
#define CP_WAIT(n)  asm volatile("cp.async.wait_group %0;" :: "n"(n) : "memory")

__device__ __forceinline__ void ldm_x4(uint32_t* r, uint32_t addr) {
    asm volatile("ldmatrix.sync.aligned.m8n8.x4.shared.b16 {%0,%1,%2,%3}, [%4];"
                 : "=r"(r[0]), "=r"(r[1]), "=r"(r[2]), "=r"(r[3]) : "r"(addr));
}
__device__ __forceinline__ void mma16816(float* c, const uint32_t* a, const uint32_t* b) {
    asm volatile(
        "mma.sync.aligned.m16n8k16.row.col.f32.f16.f16.f32 "
        "{%0,%1,%2,%3}, {%4,%5,%6,%7}, {%8,%9}, {%0,%1,%2,%3};"
        : "+f"(c[0]), "+f"(c[1]), "+f"(c[2]), "+f"(c[3])
        : "r"(a[0]), "r"(a[1]), "r"(a[2]), "r"(a[3]), "r"(b[0]), "r"(b[1]));
}

// stage one 128x32-half tile set (Ah/Al/Bh/Bl) into smem buffer via cp.async
__device__ __forceinline__ void stage_tiles(
    uint32_t sbase,
    const half* __restrict__ Ah, const half* __restrict__ Al,
    const half* __restrict__ Bh, const half* __restrict__ Bl,
    int K, int k0, int tid)
{
#pragma unroll
    for (int j = 0; j < 2; ++j) {
        const int ch  = tid + j * 256;      // 512 chunks of 16B per tile
        const int row = ch >> 2;
        const int c   = ch & 3;
        const uint32_t so = (uint32_t)(row * PITCH_B + c * 16);
        const long     go = (long)row * K + k0 + c * 8;
        cp_async16(sbase + so,              Ah + go);
        cp_async16(sbase + TILE_B + so,     Al + go);
        cp_async16(sbase + 2 * TILE_B + so, Bh + go);
        cp_async16(sbase + 3 * TILE_B + so, Bl + go);
    }
}

// ------------------------------------------------------------------------------
// D[M,Nt] = alpha * (A_hi+A_lo)[M,K] @ (B_hi+B_lo)[Nt,K]^T + biasM + biasN
// fp16x3: hh + lh + hl, fp32 accumulate. All inputs pre-split half, K-contiguous.
// SPLIT_OUT: write hi/lo half pair; else fp32.
// grid = (Nt/128, M/128, batch), 256 threads.
// ------------------------------------------------------------------------------
template <bool SPLIT_OUT>
__global__ __launch_bounds__(256, 1)
void gemm_h3(const half* __restrict__ Ahg, const half* __restrict__ Alg,
             const half* __restrict__ Bhg, const half* __restrict__ Blg,
             float* __restrict__ Df, half* __restrict__ Dh, half* __restrict__ Dl,
             const float* __restrict__ biasM, const float* __restrict__ biasN,
             int M, int Nt, int K, float alpha,
             long sA, long sB, long sD)
{
    extern __shared__ char smem[];
    const uint32_t sb = smem_u32(smem);
    const int tid = threadIdx.x;
    const int bx = blockIdx.x, by = blockIdx.y, bz = blockIdx.z;

    const long aoff = (long)bz * sA + (long)(by * 128) * K;
    const long boff = (long)bz * sB + (long)(bx * 128) * K;
    Ahg += aoff; Alg += aoff;
    Bhg += boff; Blg += boff;

    const int wid = tid >> 5, lane = tid & 31;
    const int wm = (wid >> 2) * 64;      // warp M offset
    const int wn = (wid & 3) * 32;       // warp N offset
    const int g = lane >> 2, t = lane & 3;
    // ldmatrix per-lane offset: rows = lane%16, k-half select = lane/16
    const uint32_t lmo = (uint32_t)((lane & 15) * PITCH_B + (lane >> 4) * 16);

    float acc[4][4][4];
#pragma unroll
    for (int mi = 0; mi < 4; ++mi)
#pragma unroll
        for (int ni = 0; ni < 4; ++ni)
#pragma unroll
            for (int q = 0; q < 4; ++q) acc[mi][ni][q] = 0.f;

    const int nIter = K >> 5;
    stage_tiles(sb, Ahg, Alg, Bhg, Blg, K, 0, tid);
    CP_COMMIT();

    for (int it = 0; it < nIter; ++it) {
        const int buf = it & 1;
        const bool hasNext = (it + 1 < nIter);
        if (hasNext) {
            stage_tiles(sb + (buf ^ 1) * 4 * TILE_B, Ahg, Alg, Bhg, Blg, K, (it + 1) << 5, tid);
            CP_COMMIT();
            CP_WAIT(1);
        } else {
            CP_WAIT(0);
        }
        __syncthreads();

        const uint32_t base = sb + buf * 4 * TILE_B;
#pragma unroll
        for (int kk = 0; kk < 2; ++kk) {
            const uint32_t ko = kk * 32;    // 16 halves = 32B
            uint32_t ah[4][4], al[4][4];
#pragma unroll
            for (int mi = 0; mi < 4; ++mi) {
                const uint32_t ra = base + (uint32_t)((wm + mi * 16) * PITCH_B) + ko + lmo;
                ldm_x4(ah[mi], ra);
                ldm_x4(al[mi], ra + TILE_B);
            }
            uint32_t bh[2][4], bl[2][4];
#pragma unroll
            for (int n8 = 0; n8 < 2; ++n8) {
                const uint32_t rb = base + 2 * TILE_B + (uint32_t)((wn + n8 * 16) * PITCH_B) + ko + lmo;
                ldm_x4(bh[n8], rb);
                ldm_x4(bl[n8], rb + TILE_B);
            }
#pragma unroll
            for (int mi = 0; mi < 4; ++mi)
#pragma unroll
                for (int ni = 0; ni < 4; ++ni) {
                    uint32_t bb[2]  = { bh[ni >> 1][ni & 1], bh[ni >> 1][2 + (ni & 1)] };
                    uint32_t bbl[2] = { bl[ni >> 1][ni & 1], bl[ni >> 1][2 + (ni & 1)] };
                    mma16816(acc[mi][ni], ah[mi], bb);
                    mma16816(acc[mi][ni], al[mi], bb);
                    mma16816(acc[mi][ni], ah[mi], bbl);
                }
        }
        __syncthreads();
    }

    // ---------------- epilogue ----------------
#pragma unroll
    for (int mi = 0; mi < 4; ++mi) {
        const int r0 = by * 128 + wm + mi * 16 + g;
        const float bm0 = biasM ? biasM[r0] : 0.f;
        const float bm1 = biasM ? biasM[r0 + 8] : 0.f;
        const long gr0 = (long)bz * sD + (long)r0 * Nt + bx * 128;
        const long gr1 = gr0 + 8L * Nt;
#pragma unroll
        for (int ni = 0; ni < 4; ++ni) {
            const int col = wn + ni * 8 + t * 2;
            const float bn0 = biasN ? biasN[bx * 128 + col] : 0.f;
            const float bn1 = biasN ? biasN[bx * 128 + col + 1] : 0.f;
            const float v00 = alpha * acc[mi][ni][0] + bm0 + bn0;
            const float v01 = alpha * acc[mi][ni][1] + bm0 + bn1;
            const float v10 = alpha * acc[mi][ni][2] + bm1 + bn0;
            const float v11 = alpha * acc[mi][ni][3] + bm1 + bn1;
            if (SPLIT_OUT) {
                half2 h0 = __floats2half2_rn(v00, v01);
                half2 h1 = __floats2half2_rn(v10, v11);
                float2 f0 = __half22float2(h0);
                float2 f1 = __half22float2(h1);
                half2 l0 = __floats2half2_rn(v00 - f0.x, v01 - f0.y);
                half2 l1 = __floats2half2_rn(v10 - f1.x, v11 - f1.y);
                *(half2*)&Dh[gr0 + col] = h0;
                *(half2*)&Dh[gr1 + col] = h1;
                *(half2*)&Dl[gr0 + col] = l0;
                *(half2*)&Dl[gr1 + col] = l1;
            } else {
                float2 o0 = make_float2(v00, v01);
                float2 o1 = make_float2(v10, v11);
                *(float2*)&Df[gr0 + col] = o0;
                *(float2*)&Df[gr1 + col] = o1;
            }
        }
    }
}

// ------------------------------------------------------------------------------
// v [B,C,N] -> vT hi/lo [B,N,C]
__global__ __launch_bounds__(256)
void transpose_split_kernel(const float* __restrict__ v,
                            half* __restrict__ hi, half* __restrict__ lo)
{
    __shared__ float tbuf[32][33];
    const int b = blockIdx.z;
    const int n0 = blockIdx.x * 32, c0 = blockIdx.y * 32;
    const int tx = threadIdx.x, ty = threadIdx.y;   // 32 x 8
#pragma unroll
    for (int i = 0; i < 4; ++i)
        tbuf[ty + 8 * i][tx] = v[((long)b * C_ + c0 + ty + 8 * i) * N_ + n0 + tx];
    __syncthreads();
#pragma unroll
    for (int i = 0; i < 4; ++i) {
        const float x = tbuf[tx][ty + 8 * i];
        const half h = __float2half_rn(x);
        const long o = ((long)b * N_ + n0 + ty + 8 * i) * C_ + c0 + tx;
        hi[o] = h;
        lo[o] = __float2half_rn(x - __half2float(h));
    }
}

// generic fp32 -> hi/lo half split (for weights)
__global__ __launch_bounds__(256)
void split_kernel(const float* __restrict__ x, half* __restrict__ hi,
                  half* __restrict__ lo, int n4)
{
    const int i = blockIdx.x * 256 + threadIdx.x;
    if (i >= n4) return;
    const float4 v = ((const float4*)x)[i];
    half2 h0 = __floats2half2_rn(v.x, v.y);
    half2 h1 = __floats2half2_rn(v.z, v.w);
    float2 f0 = __half22float2(h0);
    float2 f1 = __half22float2(h1);
    half2 l0 = __floats2half2_rn(v.x - f0.x, v.y - f0.y);
    half2 l1 = __floats2half2_rn(v.z - f1.x, v.w - f1.y);
    ((half2*)hi)[2 * i] = h0; ((half2*)hi)[2 * i + 1] = h1;
    ((half2*)lo)[2 * i] = l0; ((half2*)lo)[2 * i + 1] = l1;
}

// ------------------------------------------------------------------------------
__global__ __launch_bounds__(256)
void bn_stats_kernel(const float* __restrict__ Wy)
{
    const int c = blockIdx.x;
    float s = 0.f, ss = 0.f;
    for (int i = threadIdx.x; i < B_ * N_; i += 256) {
        const int b = i >> 12;
        const int n = i & (N_ - 1);
        const float x = Wy[((long)b * C_ + c) * N_ + n];
        s += x;
        ss += x * x;
    }
    __shared__ float sh_s[256], sh_q[256];
    sh_s[threadIdx.x] = s;
    sh_q[threadIdx.x] = ss;
    __syncthreads();
    for (int o = 128; o > 0; o >>= 1) {
        if (threadIdx.x < o) {
            sh_s[threadIdx.x] += sh_s[threadIdx.x + o];
            sh_q[threadIdx.x] += sh_q[threadIdx.x + o];
        }
        __syncthreads();
    }
    if (threadIdx.x == 0) {
        const float inv = 1.f / (float)(B_ * N_);
        const float m   = sh_s[0] * inv;
        const float var = fmaxf(sh_q[0] * inv - m * m, 0.f);
        bn_mean[c] = m;
        bn_rstd[c] = rsqrtf(var + EPS_);
    }
}

__global__ __launch_bounds__(256)
void bn_apply_kernel(const float* __restrict__ Wy,
                     const float* __restrict__ v,
                     const float* __restrict__ gamma,
                     const float* __restrict__ beta,
                     float* __restrict__ out)
{
    const long idx = (long)blockIdx.x * 256 + threadIdx.x;
    const long total4 = (long)B_ * C_ * N_ / 4;
    if (idx >= total4) return;
    const int c = (int)((idx * 4 / N_) % C_);
    const float sc = bn_rstd[c] * gamma[c];
    const float sh = beta[c] - bn_mean[c] * sc;
    const float4 w  = ((const float4*)Wy)[idx];
    const float4 vv = ((const float4*)v)[idx];
    float4 o;
    o.x = w.x * sc + sh + vv.x;
    o.y = w.y * sc + sh + vv.y;
    o.z = w.z * sc + sh + vv.z;
    o.w = w.w * sc + sh + vv.w;
    ((float4*)out)[idx] = o;
}

// ------------------------------------------------------------------------------
#define SYM(p, s) cudaGetSymbolAddress((void**)&p, s)

extern "C" void kernel_launch(void* const* d_in, const int* in_sizes, int n_in,
                              void* d_out, int out_size)
{
    const float* v     = (const float*)d_in[0];
    const float* Wg    = (const float*)d_in[1];
    const float* bg    = (const float*)d_in[2];
    const float* Wth   = (const float*)d_in[3];
    const float* bth   = (const float*)d_in[4];
    const float* Wph   = (const float*)d_in[5];
    const float* bph   = (const float*)d_in[6];
    const float* Ww    = (const float*)d_in[7];
    const float* bw    = (const float*)d_in[8];
    const float* gamma = (const float*)d_in[9];
    const float* beta  = (const float*)d_in[10];
    float* out = (float*)d_out;

    half *vTh, *vTl, *Wgh, *Wgl, *Wthh, *Wthl, *Wphh, *Wphl, *Wwh, *Wwl;
    half *thh, *thl, *phh, *phl, *gh, *gl, *yh, *yl, *Rh, *Rl;
    float* Wy;
    SYM(vTh, vT_hi);  SYM(vTl, vT_lo);
    SYM(Wgh, Wg_hi);  SYM(Wgl, Wg_lo);
    SYM(Wthh, Wth_hi); SYM(Wthl, Wth_lo);
    SYM(Wphh, Wph_hi); SYM(Wphl, Wph_lo);
    SYM(Wwh, Ww_hi);  SYM(Wwl, Ww_lo);
    SYM(thh, th_hi);  SYM(thl, th_lo);
    SYM(phh, ph_hi);  SYM(phl, ph_lo);
    SYM(gh,  g_hi);   SYM(gl,  g_lo);
    SYM(yh,  y_hi);   SYM(yl,  y_lo);
    SYM(Rh,  R_hi);   SYM(Rl,  R_lo);
    SYM(Wy,  Wy_buf);

    cudaFuncSetAttribute(gemm_h3<true>,  cudaFuncAttributeMaxDynamicSharedMemorySize, SMEM_GEMM_BYTES);
    cudaFuncSetAttribute(gemm_h3<false>, cudaFuncAttributeMaxDynamicSharedMemorySize, SMEM_GEMM_BYTES);

    const long sVT = (long)N_ * C_;
    const long sNC = (long)N_ * CI_;
    const long sCN = (long)CI_ * N_;
    const long sR  = (long)N_ * N_;
    const long sC  = (long)C_ * N_;

    // 0) operand prep: v -> vT hi/lo; weights -> hi/lo
    transpose_split_kernel<<<dim3(N_ / 32, C_ / 32, B_), dim3(32, 8)>>>(v, vTh, vTl);
    split_kernel<<<(CI_ * C_ / 4 + 255) / 256, 256>>>(Wg,  Wgh,  Wgl,  CI_ * C_ / 4);
    split_kernel<<<(CI_ * C_ / 4 + 255) / 256, 256>>>(Wth, Wthh, Wthl, CI_ * C_ / 4);
    split_kernel<<<(CI_ * C_ / 4 + 255) / 256, 256>>>(Wph, Wphh, Wphl, CI_ * C_ / 4);
    split_kernel<<<(C_ * CI_ / 4 + 255) / 256, 256>>>(Ww,  Wwh,  Wwl,  C_ * CI_ / 4);

    // 1) th[n,ci] = vT[n,:].Wth[ci,:] + bth   -> split out
    gemm_h3<true><<<dim3(CI_ / 128, N_ / 128, B_), 256, SMEM_GEMM_BYTES>>>(
        vTh, vTl, Wthh, Wthl, nullptr, thh, thl, nullptr, bth,
        N_, CI_, C_, 1.f, sVT, 0, sNC);
    // 2) ph[n,ci]
    gemm_h3<true><<<dim3(CI_ / 128, N_ / 128, B_), 256, SMEM_GEMM_BYTES>>>(
        vTh, vTl, Wphh, Wphl, nullptr, phh, phl, nullptr, bph,
        N_, CI_, C_, 1.f, sVT, 0, sNC);
    // 3) g[ci,n] = Wg[ci,:].vT[n,:] + bg      -> split out
    gemm_h3<true><<<dim3(N_ / 128, CI_ / 128, B_), 256, SMEM_GEMM_BYTES>>>(
        Wgh, Wgl, vTh, vTl, nullptr, gh, gl, bg, nullptr,
        CI_, N_, C_, 1.f, 0, sVT, sCN);
    // 4) R[n,m] = (RSCALE/N) th[n,:].ph[m,:]  -> split out (scaled for lo range)
    gemm_h3<true><<<dim3(N_ / 128, N_ / 128, B_), 256, SMEM_GEMM_BYTES>>>(
        thh, thl, phh, phl, nullptr, Rh, Rl, nullptr, nullptr,
        N_, N_, CI_, RSCALE / (float)N_, sNC, sNC, sR);
    // 5) y[n,ci] = (1/RSCALE) R[n,:].g[ci,:]  -> split out
    gemm_h3<true><<<dim3(CI_ / 128, N_ / 128, B_), 256, SMEM_GEMM_BYTES>>>(
        Rh, Rl, gh, gl, nullptr, yh, yl, nullptr, nullptr,
        N_, CI_, N_, 1.f / RSCALE, sR, sCN, sNC);
    // 6) Wy[c,n] = Ww[c,:].y[n,:] + bw        -> fp32 out
    gemm_h3<false><<<dim3(N_ / 128, C_ / 128, B_), 256, SMEM_GEMM_BYTES>>>(
        Wwh, Wwl, yh, yl, Wy, nullptr, nullptr, bw, nullptr,
        C_, N_, CI_, 1.f, 0, sNC, sC);

    // 7) BN stats + apply + residual
    bn_stats_kernel<<<C_, 256>>>(Wy);
    const long total4 = (long)B_ * C_ * N_ / 4;
    bn_apply_kernel<<<(int)((total4 + 255) / 256), 256>>>(Wy, v, gamma, beta, out);
}

// round 5
// speedup vs baseline: 4.0394x; 4.0394x over previous
#include <cuda_runtime.h>
#include <cuda_fp16.h>
#include <cstdint>

#define B_  4
#define C_  512
#define CI_ 256
#define N_  4096
#define EPS_ 1e-5f
#define ZSCALE 64.0f
#define SLICES 16

// ------------------------- device scratch (no allocs) -------------------------
__device__ float vT_buf[B_ * N_ * C_];                 // 32 MB [B,N,C]
__device__ float th_buf[B_ * N_ * CI_];                // 16 MB [B,N,Ci]
__device__ float ph_buf[B_ * CI_ * N_];                // 16 MB [B,Ci,N]
__device__ float g_buf [B_ * CI_ * N_];                // 16 MB [B,Ci,N]
__device__ float y_buf [B_ * N_ * CI_];                // 16 MB [B,N,Ci]
__device__ float Wy_buf[B_ * C_ * N_];                 // 32 MB [B,C,N]
__device__ float Zpart_buf[B_ * SLICES * CI_ * CI_];   // 16 MB
__device__ float Zt_buf[B_ * CI_ * CI_];               //  1 MB [B,Ci(ci),Ci(c)]
__device__ float bn_mean[C_];
__device__ float bn_rstd[C_];

// ------------------------------- GEMM config ----------------------------------
#define PITCH 40                        // halves per smem row (80B) -> conflict-free
#define TILE_HALVES (128 * PITCH)       // 5120
#define BUF_HALVES  (4 * TILE_HALVES)   // Ah, Al, Bh, Bl
#define SMEM_GEMM_BYTES (2 * BUF_HALVES * 2 + 1024)

__device__ __forceinline__ void mma16816(float* c, const uint32_t* a, const uint32_t* b) {
    asm volatile(
        "mma.sync.aligned.m16n8k16.row.col.f32.f16.f16.f32 "
        "{%0,%1,%2,%3}, {%4,%5,%6,%7}, {%8,%9}, {%0,%1,%2,%3};"
        : "+f"(c[0]), "+f"(c[1]), "+f"(c[2]), "+f"(c[3])
        : "r"(a[0]), "r"(a[1]), "r"(a[2]), "r"(a[3]), "r"(b[0]), "r"(b[1]));
}

__device__ __forceinline__ uint32_t lds_u32(const half* p, int r, int c) {
    return *(const uint32_t*)&p[r * PITCH + c];
}

// split fp32x4 -> hi/lo fp16 pairs, store to smem (lo at +TILE_HALVES)
__device__ __forceinline__ void split_store(half* base, int idx, float4 x) {
    half2 h01 = __floats2half2_rn(x.x, x.y);
    half2 h23 = __floats2half2_rn(x.z, x.w);
    float2 f01 = __half22float2(h01);
    float2 f23 = __half22float2(h23);
    half2 l01 = __floats2half2_rn(x.x - f01.x, x.y - f01.y);
    half2 l23 = __floats2half2_rn(x.z - f23.x, x.w - f23.y);
    *(half2*)&base[idx]     = h01;
    *(half2*)&base[idx + 2] = h23;
    *(half2*)&base[TILE_HALVES + idx]     = l01;
    *(half2*)&base[TILE_HALVES + idx + 2] = l23;
}

// ------------------------------------------------------------------------------
// D[M,Nt] = alpha * A[M,K] @ B[Nt,K]^T + biasM[row] + biasN[col]
// A, B row-major with row strides ldA/ldB (K contiguous). 128x128x32 tiles.
// grid = (Nt/128, M/128, nBatch*nSlices); 256 threads.
// Per-z offsets: X += b*sbX + s*slX  (b = z/nSlices, s = z%nSlices).
// fp16x3: hi*hi + lo*hi + hi*lo, fp32 accumulate -> ~1e-7 relative error.
// ------------------------------------------------------------------------------
__global__ __launch_bounds__(256, 1)
void gemm_fp16x3(const float* __restrict__ A, const float* __restrict__ Bm,
                 float* __restrict__ D,
                 const float* __restrict__ biasM, const float* __restrict__ biasN,
                 int M, int Nt, int K, int ldA, int ldB, float alpha,
                 int nSlices,
                 long sbA, long slA, long sbB, long slB, long sbD, long slD)
{
    extern __shared__ char smem[];
    half*  sh  = (half*)smem;
    float* sBM = (float*)(smem + 2 * BUF_HALVES * 2);
    float* sBN = sBM + 128;

    const int tid = threadIdx.x;
    const int bx = blockIdx.x, by = blockIdx.y, bz = blockIdx.z;
    const int bb = bz / nSlices;
    const int ss = bz % nSlices;
    A  += bb * sbA + ss * slA + (long)(by * 128) * ldA;
    Bm += bb * sbB + ss * slB + (long)(bx * 128) * ldB;
    D  += bb * sbD + ss * slD;

    if (tid < 128) {
        sBM[tid] = biasM ? biasM[by * 128 + tid] : 0.f;
        sBN[tid] = biasN ? biasN[bx * 128 + tid] : 0.f;
    }

    const int sf = tid & 7;       // k-chunk (4 floats)
    const int sr = tid >> 3;      // 0..31 (row base)
    const int nIter = K / 32;

    float4 ra[4], rb[4];
#pragma unroll
    for (int i = 0; i < 4; ++i) {
        ra[i] = *(const float4*)&A[(long)(sr + 32 * i) * ldA + sf * 4];
        rb[i] = *(const float4*)&Bm[(long)(sr + 32 * i) * ldB + sf * 4];
    }
    {
        half* Ab = sh;                       // buf 0
        half* Bb = sh + 2 * TILE_HALVES;
#pragma unroll
        for (int i = 0; i < 4; ++i) {
            const int idx = (sr + 32 * i) * PITCH + sf * 4;
            split_store(Ab, idx, ra[i]);
            split_store(Bb, idx, rb[i]);
        }
    }
    __syncthreads();

    float acc[4][4][4];
#pragma unroll
    for (int mi = 0; mi < 4; ++mi)
#pragma unroll
        for (int ni = 0; ni < 4; ++ni)
#pragma unroll
            for (int q = 0; q < 4; ++q) acc[mi][ni][q] = 0.f;

    const int wid = tid >> 5, lid = tid & 31;
    const int wm = (wid >> 2) * 64;   // warp m offset (0/64)
    const int wn = (wid & 3) * 32;    // warp n offset
    const int g = lid >> 2;           // group id 0..7
    const int t = lid & 3;            // thread in group

    for (int it = 0; it < nIter; ++it) {
        const int buf = it & 1;
        const bool hasNext = (it + 1 < nIter);
        if (hasNext) {
            const int k0 = (it + 1) * 32;
#pragma unroll
            for (int i = 0; i < 4; ++i) {
                ra[i] = *(const float4*)&A[(long)(sr + 32 * i) * ldA + k0 + sf * 4];
                rb[i] = *(const float4*)&Bm[(long)(sr + 32 * i) * ldB + k0 + sf * 4];
            }
        }

        const half* Ah = sh + buf * BUF_HALVES;
        const half* Al = Ah + TILE_HALVES;
        const half* Bh = Ah + 2 * TILE_HALVES;
        const half* Bl = Ah + 3 * TILE_HALVES;

#pragma unroll
        for (int kk = 0; kk < 2; ++kk) {
            const int kc = kk * 16 + t * 2;
            uint32_t ah[4][4], al[4][4];
#pragma unroll
            for (int mi = 0; mi < 4; ++mi) {
                const int r = wm + mi * 16 + g;
                ah[mi][0] = lds_u32(Ah, r,     kc);
                ah[mi][1] = lds_u32(Ah, r + 8, kc);
                ah[mi][2] = lds_u32(Ah, r,     kc + 8);
                ah[mi][3] = lds_u32(Ah, r + 8, kc + 8);
                al[mi][0] = lds_u32(Al, r,     kc);
                al[mi][1] = lds_u32(Al, r + 8, kc);
                al[mi][2] = lds_u32(Al, r,     kc + 8);
                al[mi][3] = lds_u32(Al, r + 8, kc + 8);
            }
            uint32_t bh[4][2], bl[4][2];
#pragma unroll
            for (int ni = 0; ni < 4; ++ni) {
                const int r = wn + ni * 8 + g;
                bh[ni][0] = lds_u32(Bh, r, kc);
                bh[ni][1] = lds_u32(Bh, r, kc + 8);
                bl[ni][0] = lds_u32(Bl, r, kc);
                bl[ni][1] = lds_u32(Bl, r, kc + 8);
            }
#pragma unroll
            for (int mi = 0; mi < 4; ++mi)
#pragma unroll
                for (int ni = 0; ni < 4; ++ni) {
                    mma16816(acc[mi][ni], ah[mi], bh[ni]);
                    mma16816(acc[mi][ni], al[mi], bh[ni]);
                    mma16816(acc[mi][ni], ah[mi], bl[ni]);
                }
        }

        if (hasNext) {
            half* Ab = sh + (buf ^ 1) * BUF_HALVES;
            half* Bb = Ab + 2 * TILE_HALVES;
#pragma unroll
            for (int i = 0; i < 4; ++i) {
                const int idx = (sr + 32 * i) * PITCH + sf * 4;
                split_store(Ab, idx, ra[i]);
                split_store(Bb, idx, rb[i]);
            }
        }
        __syncthreads();
    }

    // epilogue
#pragma unroll
    for (int mi = 0; mi < 4; ++mi) {
        const int row0 = wm + mi * 16 + g;
        const float bm0 = sBM[row0], bm1 = sBM[row0 + 8];
        const long gr0 = (long)(by * 128 + row0) * Nt + bx * 128;
        const long gr1 = gr0 + 8L * Nt;
#pragma unroll
        for (int ni = 0; ni < 4; ++ni) {
            const int col = wn + ni * 8 + t * 2;
            const float bn0 = sBN[col], bn1 = sBN[col + 1];
            float2 o0, o1;
            o0.x = alpha * acc[mi][ni][0] + bm0 + bn0;
            o0.y = alpha * acc[mi][ni][1] + bm0 + bn1;
            o1.x = alpha * acc[mi][ni][2] + bm1 + bn0;
            o1.y = alpha * acc[mi][ni][3] + bm1 + bn1;
            *(float2*)&D[gr0 + col] = o0;
            *(float2*)&D[gr1 + col] = o1;
        }
    }
}

// ------------------------------------------------------------------------------
// v [B,C,N] -> vT [B,N,C]
__global__ __launch_bounds__(256)
void transpose_kernel(const float* __restrict__ v, float* __restrict__ o)
{
    __shared__ float t[32][33];
    const int b = blockIdx.z;
    const int n0 = blockIdx.x * 32, c0 = blockIdx.y * 32;
    const int tx = threadIdx.x, ty = threadIdx.y;   // 32 x 8
#pragma unroll
    for (int i = 0; i < 4; ++i)
        t[ty + 8 * i][tx] = v[((long)b * C_ + c0 + ty + 8 * i) * N_ + n0 + tx];
    __syncthreads();
#pragma unroll
    for (int i = 0; i < 4; ++i)
        o[((long)b * N_ + n0 + ty + 8 * i) * C_ + c0 + tx] = t[tx][ty + 8 * i];
}

// ------------------------------------------------------------------------------
// reduce split-K partials: Zt[b][i] = sum_s Zpart[(b*SLICES+s)][i]
__global__ __launch_bounds__(256)
void zreduce_kernel(const float* __restrict__ part, float* __restrict__ out)
{
    const int i = blockIdx.x * 256 + threadIdx.x;     // 0..65535
    const int b = blockIdx.y;
    const float* p = part + (long)b * SLICES * (CI_ * CI_) + i;
    float s = 0.f;
#pragma unroll
    for (int k = 0; k < SLICES; ++k) s += p[(long)k * (CI_ * CI_)];
    out[(long)b * (CI_ * CI_) + i] = s;
}

// ------------------------------------------------------------------------------
__global__ __launch_bounds__(256)
void bn_stats_kernel(const float* __restrict__ Wy)
{
    const int c = blockIdx.x;
    float s = 0.f, ss = 0.f;
    for (int i = threadIdx.x; i < B_ * N_; i += 256) {
        const int b = i >> 12;
        const int n = i & (N_ - 1);
        const float x = Wy[((long)b * C_ + c) * N_ + n];
        s += x;
        ss += x * x;
    }
    __shared__ float sh_s[256], sh_q[256];
    sh_s[threadIdx.x] = s;
    sh_q[threadIdx.x] = ss;
    __syncthreads();
    for (int o = 128; o > 0; o >>= 1) {
        if (threadIdx.x < o) {
            sh_s[threadIdx.x] += sh_s[threadIdx.x + o];
            sh_q[threadIdx.x] += sh_q[threadIdx.x + o];
        }
        __syncthreads();
    }
    if (threadIdx.x == 0) {
        const float inv = 1.f / (float)(B_ * N_);
        const float m   = sh_s[0] * inv;
        const float var = fmaxf(sh_q[0] * inv - m * m, 0.f);
        bn_mean[c] = m;
        bn_rstd[c] = rsqrtf(var + EPS_);
    }
}

__global__ __launch_bounds__(256)
void bn_apply_kernel(const float* __restrict__ Wy,
                     const float* __restrict__ v,
                     const float* __restrict__ gamma,
                     const float* __restrict__ beta,
                     float* __restrict__ out)
{
    const long idx = (long)blockIdx.x * 256 + threadIdx.x;   // float4 index
    const long total4 = (long)B_ * C_ * N_ / 4;
    if (idx >= total4) return;
    const int c = (int)((idx * 4 / N_) % C_);
    const float sc = bn_rstd[c] * gamma[c];
    const float sh = beta[c] - bn_mean[c] * sc;
    const float4 w  = ((const float4*)Wy)[idx];
    const float4 vv = ((const float4*)v)[idx];
    float4 o;
    o.x = w.x * sc + sh + vv.x;
    o.y = w.y * sc + sh + vv.y;
    o.z = w.z * sc + sh + vv.z;
    o.w = w.w * sc + sh + vv.w;
    ((float4*)out)[idx] = o;
}

// ------------------------------------------------------------------------------
#define SYM(p, s) cudaGetSymbolAddress((void**)&p, s)

extern "C" void kernel_launch(void* const* d_in, const int* in_sizes, int n_in,
                              void* d_out, int out_size)
{
    const float* v     = (const float*)d_in[0];
    const float* Wg    = (const float*)d_in[1];
    const float* bg    = (const float*)d_in[2];
    const float* Wth   = (const float*)d_in[3];
    const float* bth   = (const float*)d_in[4];
    const float* Wph   = (const float*)d_in[5];
    const float* bph   = (const float*)d_in[6];
    const float* Ww    = (const float*)d_in[7];
    const float* bw    = (const float*)d_in[8];
    const float* gamma = (const float*)d_in[9];
    const float* beta  = (const float*)d_in[10];
    float* out = (float*)d_out;

    float *vT, *th, *ph, *g, *y, *Wy, *Zp, *Zt;
    SYM(vT, vT_buf);
    SYM(th, th_buf);
    SYM(ph, ph_buf);
    SYM(g,  g_buf);
    SYM(y,  y_buf);
    SYM(Wy, Wy_buf);
    SYM(Zp, Zpart_buf);
    SYM(Zt, Zt_buf);

    cudaFuncSetAttribute(gemm_fp16x3, cudaFuncAttributeMaxDynamicSharedMemorySize, SMEM_GEMM_BYTES);

    const long sVT = (long)N_ * C_;    // vT batch stride
    const long sNC = (long)N_ * CI_;   // [N,Ci]
    const long sCN = (long)CI_ * N_;   // [Ci,N]
    const long sC  = (long)C_ * N_;    // [C,N]
    const long sZ  = (long)CI_ * CI_;  // 65536

    // 0) v -> vT [B,N,C]
    transpose_kernel<<<dim3(N_ / 32, C_ / 32, B_), dim3(32, 8)>>>(v, vT);

    // 1) ph[ci,n] = Wph[ci,:].vT[n,:] + bph[ci]     (biasM)
    gemm_fp16x3<<<dim3(N_ / 128, CI_ / 128, B_), 256, SMEM_GEMM_BYTES>>>(
        Wph, vT, ph, bph, nullptr, CI_, N_, C_, C_, C_, 1.f,
        1, 0, 0, sVT, 0, sCN, 0);
    // 2) g[ci,n] = Wg[ci,:].vT[n,:] + bg[ci]
    gemm_fp16x3<<<dim3(N_ / 128, CI_ / 128, B_), 256, SMEM_GEMM_BYTES>>>(
        Wg, vT, g, bg, nullptr, CI_, N_, C_, C_, C_, 1.f,
        1, 0, 0, sVT, 0, sCN, 0);
    // 3) Zpart[z][ci,c] = (ZSCALE/N) * sum_{m in slice} g[ci,m] ph[c,m]
    //    split-K: 16 slices of 256 over m
    gemm_fp16x3<<<dim3(CI_ / 128, CI_ / 128, B_ * SLICES), 256, SMEM_GEMM_BYTES>>>(
        g, ph, Zp, nullptr, nullptr, CI_, CI_, N_ / SLICES, N_, N_, ZSCALE / (float)N_,
        SLICES, sCN, N_ / SLICES, sCN, N_ / SLICES, SLICES * sZ, sZ);
    // 4) Zt[b][ci,c] = sum_s Zpart
    zreduce_kernel<<<dim3(sZ / 256, B_), 256>>>(Zp, Zt);
    // 5) th[n,ci] = vT[n,:].Wth[ci,:] + bth[ci]     (biasN)  <- ncu capture slot
    gemm_fp16x3<<<dim3(CI_ / 128, N_ / 128, B_), 256, SMEM_GEMM_BYTES>>>(
        vT, Wth, th, nullptr, bth, N_, CI_, C_, C_, C_, 1.f,
        1, sVT, 0, 0, 0, sNC, 0);
    // 6) y[n,ci] = (1/ZSCALE) * th[n,:].Zt[ci,:]
    gemm_fp16x3<<<dim3(CI_ / 128, N_ / 128, B_), 256, SMEM_GEMM_BYTES>>>(
        th, Zt, y, nullptr, nullptr, N_, CI_, CI_, CI_, CI_, 1.f / ZSCALE,
        1, sNC, 0, sZ, 0, sNC, 0);
    // 7) Wy[c,n] = Ww[c,:].y[n,:] + bw[c]           (biasM)
    gemm_fp16x3<<<dim3(N_ / 128, C_ / 128, B_), 256, SMEM_GEMM_BYTES>>>(
        Ww, y, Wy, bw, nullptr, C_, N_, CI_, CI_, CI_, 1.f,
        1, 0, 0, sNC, 0, sC, 0);

    // 8) BN stats + apply + residual
    bn_stats_kernel<<<C_, 256>>>(Wy);
    const long total4 = (long)B_ * C_ * N_ / 4;
    bn_apply_kernel<<<(int)((total4 + 255) / 256), 256>>>(Wy, v, gamma, beta, out);
}